// round 10
// baseline (speedup 1.0000x reference)
#include <cuda_runtime.h>
#include <math.h>

#define BN    8
#define SSUP  25
#define TTGT  75
#define CCLS  5
#define NIMG  800     // 200 support + 600 target
#define NSUP  200
#define DFEAT 2304
#define EPSN  1e-8f

typedef unsigned long long u64;

// Padded intermediate layouts (zero borders, vector-load friendly):
// A1: [64][44][44] valid [0..41][0..41]
// A2: [64][24][24] valid at [h+1][w+1], h,w<=20
// A3: [64][14][16] valid at [h+1][w+1], h,w<=10
#define A1_RS 44
#define A1_PS (44*44)
#define A1_IMG (64*A1_PS)
#define A2_RS 24
#define A2_PS (24*24)
#define A2_IMG (64*A2_PS)
#define A3_RS 16
#define A3_PS (14*16)
#define A3_IMG (64*A3_PS)

__device__ __align__(16) float g_a1[NIMG * A1_IMG + 64];
__device__ __align__(16) float g_a2[NIMG * A2_IMG + 64];
__device__ __align__(16) float g_a3[NIMG * A3_IMG + 64];
__device__ __align__(16) float g_emb[NIMG * DFEAT];
__device__ __align__(16) float g_w2t[64 * 64 * 9];   // [cin][k][oc]
__device__ __align__(16) float g_w3t[64 * 64 * 9];   // [cin][k][oc]
__device__ float g_protos[BN * CCLS * DFEAT];
__device__ float g_pnorm[BN * CCLS];

// ---- packed f32x2 helpers (sm_103a FFMA2 path) ----
__device__ __forceinline__ u64 dup2(float v) {
    u64 r; unsigned u = __float_as_uint(v);
    asm("mov.b64 %0, {%1, %2};" : "=l"(r) : "r"(u), "r"(u));
    return r;
}
__device__ __forceinline__ u64 fma2(u64 a, u64 b, u64 c) {
    u64 d;
    asm("fma.rn.f32x2 %0, %1, %2, %3;" : "=l"(d) : "l"(a), "l"(b), "l"(c));
    return d;
}
__device__ __forceinline__ float2 unpack2(u64 v) {
    unsigned lo, hi;
    asm("mov.b64 {%0, %1}, %2;" : "=r"(lo), "=r"(hi) : "l"(v));
    return make_float2(__uint_as_float(lo), __uint_as_float(hi));
}

// Transpose W2/W3 from [oc][cin][k] to [cin][k][oc] once per run.
__global__ void wtrans_k(const float* __restrict__ W2, const float* __restrict__ W3)
{
    const int i = blockIdx.x * 256 + threadIdx.x;
    if (i < 36864) {
        const int oc = i % 64, k = (i / 64) % 9, cin = i / 576;
        g_w2t[i] = W2[(oc * 64 + cin) * 9 + k];
    } else if (i < 73728) {
        const int j = i - 36864;
        const int oc = j % 64, k = (j / 64) % 9, cin = j / 576;
        g_w3t[j] = W3[(oc * 64 + cin) * 9 + k];
    }
}

// Zero the padding borders of A1/A2/A3 (never touched by conv writers).
__global__ void zero_borders_k()
{
    const long long id = (long long)blockIdx.x * 256 + threadIdx.x;
    const int which = blockIdx.y;
    if (which == 0) {                         // A1: 172 border cells / chan
        if (id >= (long long)NIMG * 64 * 172) return;
        const int j = (int)(id % 172);
        const long long nc = id / 172;
        int r, c;
        if (j < 88) { r = 42 + j / 44; c = j % 44; }
        else { int j2 = j - 88; r = j2 >> 1; c = 42 + (j2 & 1); }
        g_a1[nc * A1_PS + r * A1_RS + c] = 0.f;
    } else if (which == 1) {                  // A2: 135 border cells / chan
        if (id >= (long long)NIMG * 64 * 135) return;
        const int j = (int)(id % 135);
        const long long nc = id / 135;
        int r, c;
        if (j < 72) { int rs = j / 24; r = (rs == 0) ? 0 : 21 + rs; c = j % 24; }
        else { int j2 = j - 72; r = 1 + j2 / 3; int m = j2 % 3; c = (m == 0) ? 0 : 21 + m; }
        g_a2[nc * A2_PS + r * A2_RS + c] = 0.f;
    } else {                                  // A3: 103 border cells / chan
        if (id >= (long long)NIMG * 64 * 103) return;
        const int j = (int)(id % 103);
        const long long nc = id / 103;
        int r, c;
        if (j < 48) { int rs = j / 16; r = (rs == 0) ? 0 : 11 + rs; c = j % 16; }
        else { int j2 = j - 48; r = 1 + j2 / 5; int m = j2 % 5; c = (m == 0) ? 0 : 11 + m; }
        g_a3[nc * A3_PS + r * A3_RS + c] = 0.f;
    }
}

// Layer 1 (harness input, unpadded -> masked scalar loads), writes padded A1.
__global__ void __launch_bounds__(128)
conv1_k(const float* __restrict__ xs, const float* __restrict__ xt,
        const float* __restrict__ W, const float* __restrict__ b)
{
    const int n   = blockIdx.z;
    const int cog = blockIdx.y * 8;
    const int tid = threadIdx.x;
    const int task = blockIdx.x * 128 + tid;

    __shared__ __align__(16) float sw[8 * 3 * 9];
    for (int i = tid; i < 8 * 3 * 9; i += 128) {
        const int oc = i & 7, k = (i >> 3) % 9, cin = i / 72;
        sw[i] = __ldg(W + ((size_t)(cog + oc) * 3 + cin) * 9 + k);
    }
    __syncthreads();

    if (task >= 42 * 11) return;
    const int h  = task / 11;
    const int w0 = (task % 11) * 4;
    const int r0 = 2 * h, c0 = 2 * w0;

    const float* base = (n < NSUP) ? xs + (size_t)n * 3 * 84 * 84
                                   : xt + (size_t)(n - NSUP) * 3 * 84 * 84;
    float* outp = g_a1 + (size_t)n * A1_IMG;

    u64 acc[4][4];
#pragma unroll
    for (int q = 0; q < 4; q++)
#pragma unroll
        for (int p = 0; p < 4; p++) acc[q][p] = 0ull;

#pragma unroll
    for (int cin = 0; cin < 3; cin++) {
        const float* ip = base + (size_t)cin * 84 * 84;
#pragma unroll
        for (int kh = 0; kh < 3; kh++) {
            const int r = r0 + kh;
            const bool rok = (r < 84);
            u64 dv[9];
#pragma unroll
            for (int kc = 0; kc < 9; kc++) {
                const int c = c0 + kc;
                const float v = (rok && c < 84) ? __ldg(ip + r * 84 + c) : 0.f;
                dv[kc] = dup2(v);
            }
#pragma unroll
            for (int kw = 0; kw < 3; kw++) {
                const ulonglong2* wrow = (const ulonglong2*)&sw[cin * 72 + (kh * 3 + kw) * 8];
                const ulonglong2 wA = wrow[0];
                const ulonglong2 wB = wrow[1];
                const u64 wp[4] = {wA.x, wA.y, wB.x, wB.y};
#pragma unroll
                for (int q = 0; q < 4; q++)
#pragma unroll
                    for (int p = 0; p < 4; p++)
                        acc[q][p] = fma2(dv[2 * p + kw], wp[q], acc[q][p]);
            }
        }
    }

#pragma unroll
    for (int q = 0; q < 4; q++) {
        const int co0 = cog + 2 * q;
        const float b0 = __ldg(b + co0);
        const float b1 = __ldg(b + co0 + 1);
#pragma unroll
        for (int p = 0; p < 4; p++) {
            const int w = w0 + p;
            if (w < 42) {
                const float2 v = unpack2(acc[q][p]);
                outp[(size_t)co0       * A1_PS + h * A1_RS + w] = fmaxf(v.x + b0, 0.f);
                outp[(size_t)(co0 + 1) * A1_PS + h * A1_RS + w] = fmaxf(v.y + b1, 0.f);
            }
        }
    }
}

// Layer 2 (smem-staged): block = (cout-half, image). 336 threads =
// 4 cog-groups x 84 tasks (P=6). Input staged in smem in 4-cin chunks.
__global__ void __launch_bounds__(336)
conv2s_k(const float* __restrict__ bias)
{
    const int half = blockIdx.x;              // couts [0,32) or [32,64)
    const int n    = blockIdx.y;
    const int tid  = threadIdx.x;
    const int lcog = (tid / 84) * 8;          // 0,8,16,24 within half
    const int task = tid % 84;

    __shared__ __align__(16) float si[4 * A1_PS];    // 4 cin planes (31 KB)
    __shared__ __align__(16) float sww[4 * 9 * 32];  // [cinl][k][oc32]

    const float* base = g_a1 + (size_t)n * A1_IMG;
    const int h  = task / 4;
    const int w0 = (task % 4) * 6;
    const int r0 = 2 * h, c0 = 2 * w0;

    u64 acc[4][6];
#pragma unroll
    for (int q = 0; q < 4; q++)
#pragma unroll
        for (int p = 0; p < 6; p++) acc[q][p] = 0ull;

    for (int cc = 0; cc < 16; cc++) {
        __syncthreads();
        const float4* srcp = (const float4*)(base + (size_t)cc * 4 * A1_PS);
        float4* dstp = (float4*)si;
        for (int i = tid; i < A1_PS; i += 336) dstp[i] = srcp[i];
        const float* wsrc = g_w2t + cc * 4 * 576 + half * 32;
        for (int i = tid; i < 288; i += 336) {
            const int oc4 = (i & 7) * 4;
            const int k   = (i >> 3) % 9;
            const int cl  = i / 72;
            *(float4*)&sww[cl * 288 + k * 32 + oc4] =
                *(const float4*)(wsrc + cl * 576 + k * 64 + oc4);
        }
        __syncthreads();
#pragma unroll
        for (int cl = 0; cl < 4; cl++) {
            const float* ip = si + cl * A1_PS + r0 * A1_RS + c0;
#pragma unroll
            for (int kh = 0; kh < 3; kh++) {
                float fv[16];
#pragma unroll
                for (int v = 0; v < 4; v++)
                    *(float4*)&fv[v * 4] = *(const float4*)(ip + kh * A1_RS + v * 4);
                u64 dv[13];
#pragma unroll
                for (int j = 0; j < 13; j++) dv[j] = dup2(fv[j]);
#pragma unroll
                for (int kw = 0; kw < 3; kw++) {
                    const ulonglong2* wrow =
                        (const ulonglong2*)&sww[cl * 288 + (kh * 3 + kw) * 32 + lcog];
                    const ulonglong2 wA = wrow[0];
                    const ulonglong2 wB = wrow[1];
                    const u64 wp[4] = {wA.x, wA.y, wB.x, wB.y};
#pragma unroll
                    for (int q = 0; q < 4; q++)
#pragma unroll
                        for (int p = 0; p < 6; p++)
                            acc[q][p] = fma2(dv[2 * p + kw], wp[q], acc[q][p]);
                }
            }
        }
    }

    float* outp = g_a2 + (size_t)n * A2_IMG;
#pragma unroll
    for (int q = 0; q < 4; q++) {
        const int co0 = half * 32 + lcog + 2 * q;
        const float b0 = __ldg(bias + co0);
        const float b1 = __ldg(bias + co0 + 1);
#pragma unroll
        for (int p = 0; p < 6; p++) {
            const int w = w0 + p;
            if (w < 21) {
                const float2 v = unpack2(acc[q][p]);
                outp[(size_t)co0       * A2_PS + (h + 1) * A2_RS + (w + 1)] = fmaxf(v.x + b0, 0.f);
                outp[(size_t)(co0 + 1) * A2_PS + (h + 1) * A2_RS + (w + 1)] = fmaxf(v.y + b1, 0.f);
            }
        }
    }
}

// Layer 3 (smem-staged): block = image. 176 threads = 8 cog x 22 tasks (P=6).
// Input + full-width weights staged in 8-cin chunks.
__global__ void __launch_bounds__(176)
conv3s_k(const float* __restrict__ bias)
{
    const int n    = blockIdx.x;
    const int tid  = threadIdx.x;
    const int cog  = (tid / 22) * 8;          // 0..56
    const int task = tid % 22;

    __shared__ __align__(16) float si[8 * A2_PS];    // 8 cin planes (18.4 KB)
    __shared__ __align__(16) float sww[8 * 9 * 64];  // [cinl][k][oc64] (18.4 KB)

    const float* base = g_a2 + (size_t)n * A2_IMG;
    const int h  = task / 2;
    const int w0 = (task % 2) * 6;
    const int r0 = 2 * h, c0 = 2 * w0;

    u64 acc[4][6];
#pragma unroll
    for (int q = 0; q < 4; q++)
#pragma unroll
        for (int p = 0; p < 6; p++) acc[q][p] = 0ull;

    for (int cc = 0; cc < 8; cc++) {
        __syncthreads();
        const float4* srcp = (const float4*)(base + (size_t)cc * 8 * A2_PS);
        float4* dstp = (float4*)si;
        for (int i = tid; i < 8 * A2_PS / 4; i += 176) dstp[i] = srcp[i];
        const float4* srcw = (const float4*)(g_w3t + cc * 8 * 576);
        float4* dstw = (float4*)sww;
        for (int i = tid; i < 8 * 576 / 4; i += 176) dstw[i] = srcw[i];
        __syncthreads();
#pragma unroll
        for (int cl = 0; cl < 8; cl++) {
            const float* ip = si + cl * A2_PS + r0 * A2_RS + c0;
#pragma unroll
            for (int kh = 0; kh < 3; kh++) {
                float fv[16];
#pragma unroll
                for (int v = 0; v < 4; v++)
                    *(float4*)&fv[v * 4] = *(const float4*)(ip + kh * A2_RS + v * 4);
                u64 dv[13];
#pragma unroll
                for (int j = 0; j < 13; j++) dv[j] = dup2(fv[j]);
#pragma unroll
                for (int kw = 0; kw < 3; kw++) {
                    const ulonglong2* wrow =
                        (const ulonglong2*)&sww[cl * 576 + (kh * 3 + kw) * 64 + cog];
                    const ulonglong2 wA = wrow[0];
                    const ulonglong2 wB = wrow[1];
                    const u64 wp[4] = {wA.x, wA.y, wB.x, wB.y};
#pragma unroll
                    for (int q = 0; q < 4; q++)
#pragma unroll
                        for (int p = 0; p < 6; p++)
                            acc[q][p] = fma2(dv[2 * p + kw], wp[q], acc[q][p]);
                }
            }
        }
    }

    float* outp = g_a3 + (size_t)n * A3_IMG;
#pragma unroll
    for (int q = 0; q < 4; q++) {
        const int co0 = cog + 2 * q;
        const float b0 = __ldg(bias + co0);
        const float b1 = __ldg(bias + co0 + 1);
#pragma unroll
        for (int p = 0; p < 6; p++) {
            const int w = w0 + p;
            if (w < 11) {
                const float2 v = unpack2(acc[q][p]);
                outp[(size_t)co0       * A3_PS + (h + 1) * A3_RS + (w + 1)] = fmaxf(v.x + b0, 0.f);
                outp[(size_t)(co0 + 1) * A3_PS + (h + 1) * A3_RS + (w + 1)] = fmaxf(v.y + b1, 0.f);
            }
        }
    }
}

// Layer 4 (unchanged direct path): A3 -> emb, P=6, 20 img/block.
__global__ void __launch_bounds__(120)
conv4_k(const float* __restrict__ W, const float* __restrict__ b)
{
    const int il = threadIdx.x / 6;
    const int task = threadIdx.x % 6;
    const int n = blockIdx.y * 20 + il;
    const int cog = blockIdx.x * 8;
    const int tid = threadIdx.x;

    __shared__ __align__(16) float sw[8 * 64 * 9];   // [cin][k][oc]
    for (int i = tid; i < 8 * 64 * 9; i += 120) {
        const int oc  = i & 7;
        const int k   = (i >> 3) % 9;
        const int cin = i / 72;
        sw[i] = __ldg(W + ((size_t)(cog + oc) * 64 + cin) * 9 + k);
    }
    __syncthreads();

    const float* base = g_a3 + (size_t)n * A3_IMG;
    float* outp = g_emb + (size_t)n * DFEAT;
    const int h  = task;                      // WT=1, w0=0
    const int r0 = 2 * h;

    u64 acc[4][6];
#pragma unroll
    for (int q = 0; q < 4; q++)
#pragma unroll
        for (int p = 0; p < 6; p++) acc[q][p] = 0ull;

    for (int cin = 0; cin < 64; cin++) {
        const float* ip = base + (size_t)cin * A3_PS + (size_t)r0 * A3_RS;
#pragma unroll
        for (int kh = 0; kh < 3; kh++) {
            float fv[16];
#pragma unroll
            for (int v = 0; v < 4; v++)
                *(float4*)&fv[v * 4] = *(const float4*)(ip + kh * A3_RS + v * 4);
            u64 dv[13];
#pragma unroll
            for (int j = 0; j < 13; j++) dv[j] = dup2(fv[j]);
#pragma unroll
            for (int kw = 0; kw < 3; kw++) {
                const ulonglong2* wrow = (const ulonglong2*)&sw[cin * 72 + (kh * 3 + kw) * 8];
                const ulonglong2 wA = wrow[0];
                const ulonglong2 wB = wrow[1];
                const u64 wp[4] = {wA.x, wA.y, wB.x, wB.y};
#pragma unroll
                for (int q = 0; q < 4; q++)
#pragma unroll
                    for (int p = 0; p < 6; p++)
                        acc[q][p] = fma2(dv[2 * p + kw], wp[q], acc[q][p]);
            }
        }
    }

#pragma unroll
    for (int q = 0; q < 4; q++) {
        const int co0 = cog + 2 * q;
        const float b0 = __ldg(b + co0);
        const float b1 = __ldg(b + co0 + 1);
#pragma unroll
        for (int p = 0; p < 6; p++) {
            const float2 v = unpack2(acc[q][p]);
            outp[(size_t)co0       * 36 + h * 6 + p] = fmaxf(v.x + b0, 0.f);
            outp[(size_t)(co0 + 1) * 36 + h * 6 + p] = fmaxf(v.y + b1, 0.f);
        }
    }
}

// Prototypes: proto[b][c][d] = sum_{s: y%5==c} emb / CAP ; plus ||proto||.
__global__ void proto_k(const int* __restrict__ y)
{
    const int b = blockIdx.x / CCLS;
    const int c = blockIdx.x % CCLS;
    const int tid = threadIdx.x;
    __shared__ float sel[SSUP];
    if (tid < SSUP)
        sel[tid] = ((y[b * SSUP + tid] % CCLS) == c) ? 0.2f : 0.f;
    __syncthreads();

    float sq = 0.f;
    for (int d = tid; d < DFEAT; d += 256) {
        float s = 0.f;
#pragma unroll 5
        for (int k = 0; k < SSUP; k++)
            s += sel[k] * g_emb[(size_t)(b * SSUP + k) * DFEAT + d];
        g_protos[(size_t)(b * CCLS + c) * DFEAT + d] = s;
        sq += s * s;
    }
    __shared__ float red[256];
    red[tid] = sq;
    __syncthreads();
    for (int off = 128; off > 0; off >>= 1) {
        if (tid < off) red[tid] += red[tid + off];
        __syncthreads();
    }
    if (tid == 0) g_pnorm[blockIdx.x] = sqrtf(red[0]);
}

// Cosine logits
__global__ void preds_k(float* __restrict__ out)
{
    const int bt = blockIdx.x;
    const int b  = bt / TTGT;
    const int tid = threadIdx.x;
    const float* te = g_emb + (size_t)(NSUP + bt) * DFEAT;
    const float* pr = g_protos + (size_t)b * CCLS * DFEAT;

    float dot[CCLS] = {0.f, 0.f, 0.f, 0.f, 0.f};
    float nn = 0.f;
    for (int d = tid; d < DFEAT; d += 128) {
        const float tv = te[d];
        nn += tv * tv;
#pragma unroll
        for (int c = 0; c < CCLS; c++)
            dot[c] += tv * pr[(size_t)c * DFEAT + d];
    }

    __shared__ float red[6][128];
    red[0][tid] = nn;
#pragma unroll
    for (int c = 0; c < CCLS; c++) red[c + 1][tid] = dot[c];
    __syncthreads();
    for (int off = 64; off > 0; off >>= 1) {
        if (tid < off) {
#pragma unroll
            for (int j = 0; j < 6; j++) red[j][tid] += red[j][tid + off];
        }
        __syncthreads();
    }
    if (tid < CCLS) {
        const float tn = fmaxf(sqrtf(red[0][0]), EPSN);
        const float pn = fmaxf(g_pnorm[b * CCLS + tid], EPSN);
        out[bt * CCLS + tid] = red[1 + tid][0] / (tn * pn);
    }
}

extern "C" void kernel_launch(void* const* d_in, const int* in_sizes, int n_in,
                              void* d_out, int out_size)
{
    (void)in_sizes; (void)n_in; (void)out_size;
    const float* xs = (const float*)d_in[0];
    const float* xt = (const float*)d_in[1];
    const int*   y  = (const int*)d_in[2];
    const float* W1 = (const float*)d_in[3];
    const float* b1 = (const float*)d_in[4];
    const float* W2 = (const float*)d_in[5];
    const float* b2 = (const float*)d_in[6];
    const float* W3 = (const float*)d_in[7];
    const float* b3 = (const float*)d_in[8];
    const float* W4 = (const float*)d_in[9];
    const float* b4 = (const float*)d_in[10];
    float* out = (float*)d_out;

    wtrans_k<<<288, 256>>>(W2, W3);
    zero_borders_k<<<dim3(34400, 3), 256>>>();

    conv1_k<<<dim3(4, 8, NIMG), 128>>>(xs, xt, W1, b1);
    conv2s_k<<<dim3(2, NIMG), 336>>>(b2);
    conv3s_k<<<NIMG, 176>>>(b3);
    conv4_k<<<dim3(8, NIMG / 20), 120>>>(W4, b4);

    proto_k<<<BN * CCLS, 256>>>(y);
    preds_k<<<BN * TTGT, 128>>>(out);
}

// round 11
// speedup vs baseline: 1.1709x; 1.1709x over previous
#include <cuda_runtime.h>
#include <math.h>

#define BN    8
#define SSUP  25
#define TTGT  75
#define CCLS  5
#define NIMG  800     // 200 support + 600 target
#define NSUP  200
#define DFEAT 2304
#define EPSN  1e-8f

typedef unsigned long long u64;

// Padded intermediate layouts (zero borders, vector-load friendly):
// A1: [64][44][44] valid [0..41][0..41]
// A2: [64][24][24] valid at [h+1][w+1], h,w<=20
// A3: [64][14][16] valid at [h+1][w+1], h,w<=10
#define A1_RS 44
#define A1_PS (44*44)
#define A1_IMG (64*A1_PS)
#define A2_RS 24
#define A2_PS (24*24)
#define A2_IMG (64*A2_PS)
#define A3_RS 16
#define A3_PS (14*16)
#define A3_IMG (64*A3_PS)

__device__ __align__(16) float g_a1[NIMG * A1_IMG + 64];
__device__ __align__(16) float g_a2[NIMG * A2_IMG + 64];
__device__ __align__(16) float g_a3[NIMG * A3_IMG + 64];
__device__ __align__(16) float g_emb[NIMG * DFEAT];
__device__ float g_protos[BN * CCLS * DFEAT];
__device__ float g_pnorm[BN * CCLS];

// ---- packed f32x2 helpers (sm_103a FFMA2 path) ----
__device__ __forceinline__ u64 dup2(float v) {
    u64 r; unsigned u = __float_as_uint(v);
    asm("mov.b64 %0, {%1, %2};" : "=l"(r) : "r"(u), "r"(u));
    return r;
}
__device__ __forceinline__ u64 fma2(u64 a, u64 b, u64 c) {
    u64 d;
    asm("fma.rn.f32x2 %0, %1, %2, %3;" : "=l"(d) : "l"(a), "l"(b), "l"(c));
    return d;
}
__device__ __forceinline__ float2 unpack2(u64 v) {
    unsigned lo, hi;
    asm("mov.b64 {%0, %1}, %2;" : "=r"(lo), "=r"(hi) : "l"(v));
    return make_float2(__uint_as_float(lo), __uint_as_float(hi));
}

// Zero the padding borders of A1/A2/A3 (never touched by conv writers).
__global__ void zero_borders_k()
{
    const long long id = (long long)blockIdx.x * 256 + threadIdx.x;
    const int which = blockIdx.y;
    if (which == 0) {                         // A1: 172 border cells / chan
        if (id >= (long long)NIMG * 64 * 172) return;
        const int j = (int)(id % 172);
        const long long nc = id / 172;
        int r, c;
        if (j < 88) { r = 42 + j / 44; c = j % 44; }
        else { int j2 = j - 88; r = j2 >> 1; c = 42 + (j2 & 1); }
        g_a1[nc * A1_PS + r * A1_RS + c] = 0.f;
    } else if (which == 1) {                  // A2: 135 border cells / chan
        if (id >= (long long)NIMG * 64 * 135) return;
        const int j = (int)(id % 135);
        const long long nc = id / 135;
        int r, c;
        if (j < 72) { int rs = j / 24; r = (rs == 0) ? 0 : 21 + rs; c = j % 24; }
        else { int j2 = j - 72; r = 1 + j2 / 3; int m = j2 % 3; c = (m == 0) ? 0 : 21 + m; }
        g_a2[nc * A2_PS + r * A2_RS + c] = 0.f;
    } else {                                  // A3: 103 border cells / chan
        if (id >= (long long)NIMG * 64 * 103) return;
        const int j = (int)(id % 103);
        const long long nc = id / 103;
        int r, c;
        if (j < 48) { int rs = j / 16; r = (rs == 0) ? 0 : 11 + rs; c = j % 16; }
        else { int j2 = j - 48; r = 1 + j2 / 5; int m = j2 % 5; c = (m == 0) ? 0 : 11 + m; }
        g_a3[nc * A3_PS + r * A3_RS + c] = 0.f;
    }
}

// Software-pipelined direct conv (padded input, stride 2, 3x3, no bounds
// checks). Double-buffered register prefetch across the cin loop: loads for
// cin+1 are issued before the FMA wall of cin, hiding L2 latency.
// Weights staged once in smem as [cin][k][oc], read as LDS.64 oc-pairs.
// Each thread: 4 oc-pairs (FFMA2) x 4 output pixels. (Proven R6 inner loop.)
template <int CIN, int RS, int PS, int HOUT, int ORS, int OPS, int OSH, int TPB>
__device__ __forceinline__ void conv_body_pf(
    const float* __restrict__ base,
    const float* __restrict__ W,
    const float* __restrict__ bias,
    float* __restrict__ outp,
    int cog, int task)
{
    constexpr int WT = (HOUT + 3) / 4;
    const int tid = threadIdx.x;

    __shared__ __align__(16) float sw[8 * CIN * 9];   // [cin][k][oc]
    for (int i = tid; i < 8 * CIN * 9; i += TPB) {
        const int oc  = i & 7;
        const int k   = (i >> 3) % 9;
        const int cin = i / 72;
        sw[i] = __ldg(W + ((size_t)(cog + oc) * CIN + cin) * 9 + k);
    }
    __syncthreads();

    if (task >= HOUT * WT) return;
    const int h  = task / WT;
    const int w0 = (task % WT) * 4;
    const int r0 = 2 * h;
    const int c0 = 2 * w0;

    u64 acc[4][4];
#pragma unroll
    for (int q = 0; q < 4; q++)
#pragma unroll
        for (int p = 0; p < 4; p++) acc[q][p] = 0ull;

    const float* ip0 = base + (size_t)r0 * RS + c0;

    float4 bufA[9], bufB[9];
    // preload cin = 0
#pragma unroll
    for (int kh = 0; kh < 3; kh++)
#pragma unroll
        for (int v = 0; v < 3; v++)
            bufA[kh * 3 + v] = *(const float4*)(ip0 + kh * RS + v * 4);

#pragma unroll 1
    for (int cin = 0; cin < CIN; cin += 2) {
        // prefetch cin+1 into bufB (issued before bufA's FMA wall)
        {
            const float* ipn = ip0 + (size_t)(cin + 1) * PS;
#pragma unroll
            for (int kh = 0; kh < 3; kh++)
#pragma unroll
                for (int v = 0; v < 3; v++)
                    bufB[kh * 3 + v] = *(const float4*)(ipn + kh * RS + v * 4);
        }
        // compute cin (bufA)
#pragma unroll
        for (int kh = 0; kh < 3; kh++) {
            const float* fr = (const float*)&bufA[kh * 3];
            u64 dv[9];
#pragma unroll
            for (int j = 0; j < 9; j++) dv[j] = dup2(fr[j]);
#pragma unroll
            for (int kw = 0; kw < 3; kw++) {
                const u64* wrow = (const u64*)&sw[cin * 72 + (kh * 3 + kw) * 8];
#pragma unroll
                for (int q = 0; q < 4; q++) {
                    const u64 wp = wrow[q];
#pragma unroll
                    for (int p = 0; p < 4; p++)
                        acc[q][p] = fma2(dv[2 * p + kw], wp, acc[q][p]);
                }
            }
        }
        // prefetch cin+2 into bufA
        if (cin + 2 < CIN) {
            const float* ipn = ip0 + (size_t)(cin + 2) * PS;
#pragma unroll
            for (int kh = 0; kh < 3; kh++)
#pragma unroll
                for (int v = 0; v < 3; v++)
                    bufA[kh * 3 + v] = *(const float4*)(ipn + kh * RS + v * 4);
        }
        // compute cin+1 (bufB)
#pragma unroll
        for (int kh = 0; kh < 3; kh++) {
            const float* fr = (const float*)&bufB[kh * 3];
            u64 dv[9];
#pragma unroll
            for (int j = 0; j < 9; j++) dv[j] = dup2(fr[j]);
#pragma unroll
            for (int kw = 0; kw < 3; kw++) {
                const u64* wrow = (const u64*)&sw[(cin + 1) * 72 + (kh * 3 + kw) * 8];
#pragma unroll
                for (int q = 0; q < 4; q++) {
                    const u64 wp = wrow[q];
#pragma unroll
                    for (int p = 0; p < 4; p++)
                        acc[q][p] = fma2(dv[2 * p + kw], wp, acc[q][p]);
                }
            }
        }
    }

#pragma unroll
    for (int q = 0; q < 4; q++) {
        const int co0 = cog + 2 * q;
        const float b0 = __ldg(bias + co0);
        const float b1 = __ldg(bias + co0 + 1);
#pragma unroll
        for (int p = 0; p < 4; p++) {
            const int w = w0 + p;
            if (w < HOUT) {
                const float2 v = unpack2(acc[q][p]);
                outp[((size_t)co0       * OPS) + (h + OSH) * ORS + (w + OSH)] = fmaxf(v.x + b0, 0.f);
                outp[((size_t)(co0 + 1) * OPS) + (h + OSH) * ORS + (w + OSH)] = fmaxf(v.y + b1, 0.f);
            }
        }
    }
}

// Layer 1 (harness input, unpadded -> masked scalar loads), writes padded A1.
__global__ void __launch_bounds__(128)
conv1_k(const float* __restrict__ xs, const float* __restrict__ xt,
        const float* __restrict__ W, const float* __restrict__ b)
{
    const int n   = blockIdx.z;
    const int cog = blockIdx.y * 8;
    const int tid = threadIdx.x;
    const int task = blockIdx.x * 128 + tid;

    __shared__ __align__(16) float sw[8 * 3 * 9];
    for (int i = tid; i < 8 * 3 * 9; i += 128) {
        const int oc = i & 7, k = (i >> 3) % 9, cin = i / 72;
        sw[i] = __ldg(W + ((size_t)(cog + oc) * 3 + cin) * 9 + k);
    }
    __syncthreads();

    if (task >= 42 * 11) return;
    const int h  = task / 11;
    const int w0 = (task % 11) * 4;
    const int r0 = 2 * h, c0 = 2 * w0;

    const float* base = (n < NSUP) ? xs + (size_t)n * 3 * 84 * 84
                                   : xt + (size_t)(n - NSUP) * 3 * 84 * 84;
    float* outp = g_a1 + (size_t)n * A1_IMG;

    u64 acc[4][4];
#pragma unroll
    for (int q = 0; q < 4; q++)
#pragma unroll
        for (int p = 0; p < 4; p++) acc[q][p] = 0ull;

#pragma unroll
    for (int cin = 0; cin < 3; cin++) {
        const float* ip = base + (size_t)cin * 84 * 84;
#pragma unroll
        for (int kh = 0; kh < 3; kh++) {
            const int r = r0 + kh;
            const bool rok = (r < 84);
            u64 dv[9];
#pragma unroll
            for (int kc = 0; kc < 9; kc++) {
                const int c = c0 + kc;
                const float v = (rok && c < 84) ? __ldg(ip + r * 84 + c) : 0.f;
                dv[kc] = dup2(v);
            }
#pragma unroll
            for (int kw = 0; kw < 3; kw++) {
                const u64* wrow = (const u64*)&sw[cin * 72 + (kh * 3 + kw) * 8];
#pragma unroll
                for (int q = 0; q < 4; q++) {
                    const u64 wp = wrow[q];
#pragma unroll
                    for (int p = 0; p < 4; p++)
                        acc[q][p] = fma2(dv[2 * p + kw], wp, acc[q][p]);
                }
            }
        }
    }

#pragma unroll
    for (int q = 0; q < 4; q++) {
        const int co0 = cog + 2 * q;
        const float b0 = __ldg(b + co0);
        const float b1 = __ldg(b + co0 + 1);
#pragma unroll
        for (int p = 0; p < 4; p++) {
            const int w = w0 + p;
            if (w < 42) {
                const float2 v = unpack2(acc[q][p]);
                outp[(size_t)co0       * A1_PS + h * A1_RS + w] = fmaxf(v.x + b0, 0.f);
                outp[(size_t)(co0 + 1) * A1_PS + h * A1_RS + w] = fmaxf(v.y + b1, 0.f);
            }
        }
    }
}

// Layer 2: A1 -> A2, 126 tasks/img, 2 img/block (168 threads, proven config)
__global__ void __launch_bounds__(168)
conv2_k(const float* __restrict__ W, const float* __restrict__ b)
{
    const int il = threadIdx.x / 84;
    const int task = threadIdx.x % 84;
    const int n = blockIdx.y * 2 + il;
    const int cog = blockIdx.x * 8;
    // NOTE: tasks 84..125 of each image handled by second task range below
    // (TPB=168 covers 2 images x 84; remaining 42 tasks/img go to 2nd grid.x half)
    conv_body_pf<64, A1_RS, A1_PS, 21, A2_RS, A2_PS, 1, 168>(
        g_a1 + (size_t)n * A1_IMG, W, b, g_a2 + (size_t)n * A2_IMG, cog,
        blockIdx.z * 84 + task);
}

// Layer 3: A2 -> A3, 33 tasks/img, 4 img/block (132 threads)
__global__ void __launch_bounds__(132)
conv3_k(const float* __restrict__ W, const float* __restrict__ b)
{
    const int il = threadIdx.x / 33;
    const int task = threadIdx.x % 33;
    const int n = blockIdx.y * 4 + il;
    const int cog = blockIdx.x * 8;
    conv_body_pf<64, A2_RS, A2_PS, 11, A3_RS, A3_PS, 1, 132>(
        g_a2 + (size_t)n * A2_IMG, W, b, g_a3 + (size_t)n * A3_IMG, cog, task);
}

// Layer 4: A3 -> emb (dense), 12 tasks/img, 10 img/block (120 threads)
__global__ void __launch_bounds__(120)
conv4_k(const float* __restrict__ W, const float* __restrict__ b)
{
    const int il = threadIdx.x / 12;
    const int task = threadIdx.x % 12;
    const int n = blockIdx.y * 10 + il;
    const int cog = blockIdx.x * 8;
    conv_body_pf<64, A3_RS, A3_PS, 6, 6, 36, 0, 120>(
        g_a3 + (size_t)n * A3_IMG, W, b, g_emb + (size_t)n * DFEAT, cog, task);
}

// Prototypes: proto[b][c][d] = sum_{s: y%5==c} emb / CAP ; plus ||proto||.
__global__ void proto_k(const int* __restrict__ y)
{
    const int b = blockIdx.x / CCLS;
    const int c = blockIdx.x % CCLS;
    const int tid = threadIdx.x;
    __shared__ float sel[SSUP];
    if (tid < SSUP)
        sel[tid] = ((y[b * SSUP + tid] % CCLS) == c) ? 0.2f : 0.f;
    __syncthreads();

    float sq = 0.f;
    for (int d = tid; d < DFEAT; d += 256) {
        float s = 0.f;
#pragma unroll 5
        for (int k = 0; k < SSUP; k++)
            s += sel[k] * g_emb[(size_t)(b * SSUP + k) * DFEAT + d];
        g_protos[(size_t)(b * CCLS + c) * DFEAT + d] = s;
        sq += s * s;
    }
    __shared__ float red[256];
    red[tid] = sq;
    __syncthreads();
    for (int off = 128; off > 0; off >>= 1) {
        if (tid < off) red[tid] += red[tid + off];
        __syncthreads();
    }
    if (tid == 0) g_pnorm[blockIdx.x] = sqrtf(red[0]);
}

// Cosine logits
__global__ void preds_k(float* __restrict__ out)
{
    const int bt = blockIdx.x;
    const int b  = bt / TTGT;
    const int tid = threadIdx.x;
    const float* te = g_emb + (size_t)(NSUP + bt) * DFEAT;
    const float* pr = g_protos + (size_t)b * CCLS * DFEAT;

    float dot[CCLS] = {0.f, 0.f, 0.f, 0.f, 0.f};
    float nn = 0.f;
    for (int d = tid; d < DFEAT; d += 128) {
        const float tv = te[d];
        nn += tv * tv;
#pragma unroll
        for (int c = 0; c < CCLS; c++)
            dot[c] += tv * pr[(size_t)c * DFEAT + d];
    }

    __shared__ float red[6][128];
    red[0][tid] = nn;
#pragma unroll
    for (int c = 0; c < CCLS; c++) red[c + 1][tid] = dot[c];
    __syncthreads();
    for (int off = 64; off > 0; off >>= 1) {
        if (tid < off) {
#pragma unroll
            for (int j = 0; j < 6; j++) red[j][tid] += red[j][tid + off];
        }
        __syncthreads();
    }
    if (tid < CCLS) {
        const float tn = fmaxf(sqrtf(red[0][0]), EPSN);
        const float pn = fmaxf(g_pnorm[b * CCLS + tid], EPSN);
        out[bt * CCLS + tid] = red[1 + tid][0] / (tn * pn);
    }
}

extern "C" void kernel_launch(void* const* d_in, const int* in_sizes, int n_in,
                              void* d_out, int out_size)
{
    (void)in_sizes; (void)n_in; (void)out_size;
    const float* xs = (const float*)d_in[0];
    const float* xt = (const float*)d_in[1];
    const int*   y  = (const int*)d_in[2];
    const float* W1 = (const float*)d_in[3];
    const float* b1 = (const float*)d_in[4];
    const float* W2 = (const float*)d_in[5];
    const float* b2 = (const float*)d_in[6];
    const float* W3 = (const float*)d_in[7];
    const float* b3 = (const float*)d_in[8];
    const float* W4 = (const float*)d_in[9];
    const float* b4 = (const float*)d_in[10];
    float* out = (float*)d_out;

    zero_borders_k<<<dim3(34400, 3), 256>>>();

    conv1_k<<<dim3(4, 8, NIMG), 128>>>(xs, xt, W1, b1);
    // conv2: 126 tasks/img split as z=0 -> tasks 0..83, z=1 -> tasks 84..125
    conv2_k<<<dim3(8, NIMG / 2, 2), 168>>>(W2, b2);
    conv3_k<<<dim3(8, NIMG / 4), 132>>>(W3, b3);
    conv4_k<<<dim3(8, NIMG / 10), 120>>>(W4, b4);

    proto_k<<<BN * CCLS, 256>>>(y);
    preds_k<<<BN * TTGT, 128>>>(out);
}

// round 12
// speedup vs baseline: 1.5161x; 1.2948x over previous
#include <cuda_runtime.h>
#include <math.h>

#define BN    8
#define SSUP  25
#define TTGT  75
#define CCLS  5
#define NIMG  800     // 200 support + 600 target
#define NSUP  200
#define DFEAT 2304
#define EPSN  1e-8f

typedef unsigned long long u64;

// Padded intermediate layouts (zero borders, vector-load friendly):
// A1: [64][44][44] valid [0..41][0..41]
// A2: [64][24][24] valid at [h+1][w+1], h,w<=20
// A3: [64][14][16] valid at [h+1][w+1], h,w<=10
#define A1_RS 44
#define A1_PS (44*44)
#define A1_IMG (64*A1_PS)
#define A2_RS 24
#define A2_PS (24*24)
#define A2_IMG (64*A2_PS)
#define A3_RS 16
#define A3_PS (14*16)
#define A3_IMG (64*A3_PS)

__device__ __align__(16) float g_a1[NIMG * A1_IMG + 64];
__device__ __align__(16) float g_a2[NIMG * A2_IMG + 64];
__device__ __align__(16) float g_a3[NIMG * A3_IMG + 64];
__device__ __align__(16) float g_emb[NIMG * DFEAT];
__device__ float g_protos[BN * CCLS * DFEAT];
__device__ float g_pnorm[BN * CCLS];

// ---- packed f32x2 helpers (sm_103a FFMA2 path) ----
__device__ __forceinline__ u64 dup2(float v) {
    u64 r; unsigned u = __float_as_uint(v);
    asm("mov.b64 %0, {%1, %2};" : "=l"(r) : "r"(u), "r"(u));
    return r;
}
__device__ __forceinline__ u64 fma2(u64 a, u64 b, u64 c) {
    u64 d;
    asm("fma.rn.f32x2 %0, %1, %2, %3;" : "=l"(d) : "l"(a), "l"(b), "l"(c));
    return d;
}
__device__ __forceinline__ float2 unpack2(u64 v) {
    unsigned lo, hi;
    asm("mov.b64 {%0, %1}, %2;" : "=r"(lo), "=r"(hi) : "l"(v));
    return make_float2(__uint_as_float(lo), __uint_as_float(hi));
}

// Zero the padding borders of A1/A2/A3 (never touched by conv writers).
__global__ void zero_borders_k()
{
    const long long id = (long long)blockIdx.x * 256 + threadIdx.x;
    const int which = blockIdx.y;
    if (which == 0) {                         // A1: 172 border cells / chan
        if (id >= (long long)NIMG * 64 * 172) return;
        const int j = (int)(id % 172);
        const long long nc = id / 172;
        int r, c;
        if (j < 88) { r = 42 + j / 44; c = j % 44; }
        else { int j2 = j - 88; r = j2 >> 1; c = 42 + (j2 & 1); }
        g_a1[nc * A1_PS + r * A1_RS + c] = 0.f;
    } else if (which == 1) {                  // A2: 135 border cells / chan
        if (id >= (long long)NIMG * 64 * 135) return;
        const int j = (int)(id % 135);
        const long long nc = id / 135;
        int r, c;
        if (j < 72) { int rs = j / 24; r = (rs == 0) ? 0 : 21 + rs; c = j % 24; }
        else { int j2 = j - 72; r = 1 + j2 / 3; int m = j2 % 3; c = (m == 0) ? 0 : 21 + m; }
        g_a2[nc * A2_PS + r * A2_RS + c] = 0.f;
    } else {                                  // A3: 103 border cells / chan
        if (id >= (long long)NIMG * 64 * 103) return;
        const int j = (int)(id % 103);
        const long long nc = id / 103;
        int r, c;
        if (j < 48) { int rs = j / 16; r = (rs == 0) ? 0 : 11 + rs; c = j % 16; }
        else { int j2 = j - 48; r = 1 + j2 / 5; int m = j2 % 5; c = (m == 0) ? 0 : 11 + m; }
        g_a3[nc * A3_PS + r * A3_RS + c] = 0.f;
    }
}

// Direct conv, padded input, stride 2, 3x3, no bounds checks.
// COG=16: each thread computes 16 output channels (8 FFMA2 oc-pairs) x 4
// pixels -> 2x more math per input byte than COG=8. Weights in smem as
// [cin][k][oc16], read as broadcast LDS.128 (4 per (cin,k)).
template <int CIN, int RS, int PS, int HOUT, int ORS, int OPS, int OSH, int TPB>
__device__ __forceinline__ void conv_body16(
    const float* __restrict__ base,
    const float* __restrict__ W,
    const float* __restrict__ bias,
    float* __restrict__ outp,
    int cog, int task)
{
    constexpr int WT = (HOUT + 3) / 4;
    const int tid = threadIdx.x;

    __shared__ __align__(16) float sw[16 * CIN * 9];  // [cin][k][oc16]
    for (int i = tid; i < 16 * CIN * 9; i += TPB) {
        const int oc  = i & 15;
        const int k   = (i >> 4) % 9;
        const int cin = i / 144;
        sw[i] = __ldg(W + ((size_t)(cog + oc) * CIN + cin) * 9 + k);
    }
    __syncthreads();

    if (task >= HOUT * WT) return;
    const int h  = task / WT;
    const int w0 = (task % WT) * 4;
    const int r0 = 2 * h;
    const int c0 = 2 * w0;

    u64 acc[8][4];
#pragma unroll
    for (int q = 0; q < 8; q++)
#pragma unroll
        for (int p = 0; p < 4; p++) acc[q][p] = 0ull;

    const float* ip0 = base + (size_t)r0 * RS + c0;

#pragma unroll 2
    for (int cin = 0; cin < CIN; cin++) {
        const float* ip = ip0 + (size_t)cin * PS;
#pragma unroll
        for (int kh = 0; kh < 3; kh++) {
            float fv[12];
#pragma unroll
            for (int v = 0; v < 3; v++)
                *(float4*)&fv[v * 4] = *(const float4*)(ip + kh * RS + v * 4);
            u64 dv[9];
#pragma unroll
            for (int j = 0; j < 9; j++) dv[j] = dup2(fv[j]);
#pragma unroll
            for (int kw = 0; kw < 3; kw++) {
                const ulonglong2* wrow =
                    (const ulonglong2*)&sw[(cin * 9 + kh * 3 + kw) * 16];
                const ulonglong2 wA = wrow[0];
                const ulonglong2 wB = wrow[1];
                const ulonglong2 wC = wrow[2];
                const ulonglong2 wD = wrow[3];
                const u64 wp[8] = {wA.x, wA.y, wB.x, wB.y, wC.x, wC.y, wD.x, wD.y};
#pragma unroll
                for (int q = 0; q < 8; q++)
#pragma unroll
                    for (int p = 0; p < 4; p++)
                        acc[q][p] = fma2(dv[2 * p + kw], wp[q], acc[q][p]);
            }
        }
    }

#pragma unroll
    for (int q = 0; q < 8; q++) {
        const int co0 = cog + 2 * q;
        const float b0 = __ldg(bias + co0);
        const float b1 = __ldg(bias + co0 + 1);
#pragma unroll
        for (int p = 0; p < 4; p++) {
            const int w = w0 + p;
            if (w < HOUT) {
                const float2 v = unpack2(acc[q][p]);
                outp[((size_t)co0       * OPS) + (h + OSH) * ORS + (w + OSH)] = fmaxf(v.x + b0, 0.f);
                outp[((size_t)(co0 + 1) * OPS) + (h + OSH) * ORS + (w + OSH)] = fmaxf(v.y + b1, 0.f);
            }
        }
    }
}

// Layer 1 (harness input, unpadded -> masked scalar loads), writes padded A1.
__global__ void __launch_bounds__(128)
conv1_k(const float* __restrict__ xs, const float* __restrict__ xt,
        const float* __restrict__ W, const float* __restrict__ b)
{
    const int n   = blockIdx.z;
    const int cog = blockIdx.y * 8;
    const int tid = threadIdx.x;
    const int task = blockIdx.x * 128 + tid;

    __shared__ __align__(16) float sw[8 * 3 * 9];
    for (int i = tid; i < 8 * 3 * 9; i += 128) {
        const int oc = i & 7, k = (i >> 3) % 9, cin = i / 72;
        sw[i] = __ldg(W + ((size_t)(cog + oc) * 3 + cin) * 9 + k);
    }
    __syncthreads();

    if (task >= 42 * 11) return;
    const int h  = task / 11;
    const int w0 = (task % 11) * 4;
    const int r0 = 2 * h, c0 = 2 * w0;

    const float* base = (n < NSUP) ? xs + (size_t)n * 3 * 84 * 84
                                   : xt + (size_t)(n - NSUP) * 3 * 84 * 84;
    float* outp = g_a1 + (size_t)n * A1_IMG;

    u64 acc[4][4];
#pragma unroll
    for (int q = 0; q < 4; q++)
#pragma unroll
        for (int p = 0; p < 4; p++) acc[q][p] = 0ull;

#pragma unroll
    for (int cin = 0; cin < 3; cin++) {
        const float* ip = base + (size_t)cin * 84 * 84;
#pragma unroll
        for (int kh = 0; kh < 3; kh++) {
            const int r = r0 + kh;
            const bool rok = (r < 84);
            u64 dv[9];
#pragma unroll
            for (int kc = 0; kc < 9; kc++) {
                const int c = c0 + kc;
                const float v = (rok && c < 84) ? __ldg(ip + r * 84 + c) : 0.f;
                dv[kc] = dup2(v);
            }
#pragma unroll
            for (int kw = 0; kw < 3; kw++) {
                const u64* wrow = (const u64*)&sw[cin * 72 + (kh * 3 + kw) * 8];
#pragma unroll
                for (int q = 0; q < 4; q++) {
                    const u64 wp = wrow[q];
#pragma unroll
                    for (int p = 0; p < 4; p++)
                        acc[q][p] = fma2(dv[2 * p + kw], wp, acc[q][p]);
                }
            }
        }
    }

#pragma unroll
    for (int q = 0; q < 4; q++) {
        const int co0 = cog + 2 * q;
        const float b0 = __ldg(b + co0);
        const float b1 = __ldg(b + co0 + 1);
#pragma unroll
        for (int p = 0; p < 4; p++) {
            const int w = w0 + p;
            if (w < 42) {
                const float2 v = unpack2(acc[q][p]);
                outp[(size_t)co0       * A1_PS + h * A1_RS + w] = fmaxf(v.x + b0, 0.f);
                outp[(size_t)(co0 + 1) * A1_PS + h * A1_RS + w] = fmaxf(v.y + b1, 0.f);
            }
        }
    }
}

// Layer 2: A1 -> A2, 126 tasks/img, 1 img/block, 4 cog16-groups
__global__ void __launch_bounds__(128, 3)
conv2_k(const float* __restrict__ W, const float* __restrict__ b)
{
    const int n = blockIdx.y;
    const int cog = blockIdx.x * 16;
    conv_body16<64, A1_RS, A1_PS, 21, A2_RS, A2_PS, 1, 128>(
        g_a1 + (size_t)n * A1_IMG, W, b, g_a2 + (size_t)n * A2_IMG,
        cog, threadIdx.x);
}

// Layer 3: A2 -> A3, 33 tasks/img, 4 img/block (132 threads)
__global__ void __launch_bounds__(132, 3)
conv3_k(const float* __restrict__ W, const float* __restrict__ b)
{
    const int il = threadIdx.x / 33;
    const int task = threadIdx.x % 33;
    const int n = blockIdx.y * 4 + il;
    const int cog = blockIdx.x * 16;
    conv_body16<64, A2_RS, A2_PS, 11, A3_RS, A3_PS, 1, 132>(
        g_a2 + (size_t)n * A2_IMG, W, b, g_a3 + (size_t)n * A3_IMG, cog, task);
}

// Layer 4: A3 -> emb (dense), 12 tasks/img, 10 img/block (120 threads)
__global__ void __launch_bounds__(120, 3)
conv4_k(const float* __restrict__ W, const float* __restrict__ b)
{
    const int il = threadIdx.x / 12;
    const int task = threadIdx.x % 12;
    const int n = blockIdx.y * 10 + il;
    const int cog = blockIdx.x * 16;
    conv_body16<64, A3_RS, A3_PS, 6, 6, 36, 0, 120>(
        g_a3 + (size_t)n * A3_IMG, W, b, g_emb + (size_t)n * DFEAT, cog, task);
}

// Prototypes: proto[b][c][d] = sum_{s: y%5==c} emb / CAP ; plus ||proto||.
__global__ void proto_k(const int* __restrict__ y)
{
    const int b = blockIdx.x / CCLS;
    const int c = blockIdx.x % CCLS;
    const int tid = threadIdx.x;
    __shared__ float sel[SSUP];
    if (tid < SSUP)
        sel[tid] = ((y[b * SSUP + tid] % CCLS) == c) ? 0.2f : 0.f;
    __syncthreads();

    float sq = 0.f;
    for (int d = tid; d < DFEAT; d += 256) {
        float s = 0.f;
#pragma unroll 5
        for (int k = 0; k < SSUP; k++)
            s += sel[k] * g_emb[(size_t)(b * SSUP + k) * DFEAT + d];
        g_protos[(size_t)(b * CCLS + c) * DFEAT + d] = s;
        sq += s * s;
    }
    __shared__ float red[256];
    red[tid] = sq;
    __syncthreads();
    for (int off = 128; off > 0; off >>= 1) {
        if (tid < off) red[tid] += red[tid + off];
        __syncthreads();
    }
    if (tid == 0) g_pnorm[blockIdx.x] = sqrtf(red[0]);
}

// Cosine logits
__global__ void preds_k(float* __restrict__ out)
{
    const int bt = blockIdx.x;
    const int b  = bt / TTGT;
    const int tid = threadIdx.x;
    const float* te = g_emb + (size_t)(NSUP + bt) * DFEAT;
    const float* pr = g_protos + (size_t)b * CCLS * DFEAT;

    float dot[CCLS] = {0.f, 0.f, 0.f, 0.f, 0.f};
    float nn = 0.f;
    for (int d = tid; d < DFEAT; d += 128) {
        const float tv = te[d];
        nn += tv * tv;
#pragma unroll
        for (int c = 0; c < CCLS; c++)
            dot[c] += tv * pr[(size_t)c * DFEAT + d];
    }

    __shared__ float red[6][128];
    red[0][tid] = nn;
#pragma unroll
    for (int c = 0; c < CCLS; c++) red[c + 1][tid] = dot[c];
    __syncthreads();
    for (int off = 64; off > 0; off >>= 1) {
        if (tid < off) {
#pragma unroll
            for (int j = 0; j < 6; j++) red[j][tid] += red[j][tid + off];
        }
        __syncthreads();
    }
    if (tid < CCLS) {
        const float tn = fmaxf(sqrtf(red[0][0]), EPSN);
        const float pn = fmaxf(g_pnorm[b * CCLS + tid], EPSN);
        out[bt * CCLS + tid] = red[1 + tid][0] / (tn * pn);
    }
}

extern "C" void kernel_launch(void* const* d_in, const int* in_sizes, int n_in,
                              void* d_out, int out_size)
{
    (void)in_sizes; (void)n_in; (void)out_size;
    const float* xs = (const float*)d_in[0];
    const float* xt = (const float*)d_in[1];
    const int*   y  = (const int*)d_in[2];
    const float* W1 = (const float*)d_in[3];
    const float* b1 = (const float*)d_in[4];
    const float* W2 = (const float*)d_in[5];
    const float* b2 = (const float*)d_in[6];
    const float* W3 = (const float*)d_in[7];
    const float* b3 = (const float*)d_in[8];
    const float* W4 = (const float*)d_in[9];
    const float* b4 = (const float*)d_in[10];
    float* out = (float*)d_out;

    zero_borders_k<<<dim3(34400, 3), 256>>>();

    conv1_k<<<dim3(4, 8, NIMG), 128>>>(xs, xt, W1, b1);
    conv2_k<<<dim3(4, NIMG), 128>>>(W2, b2);
    conv3_k<<<dim3(4, NIMG / 4), 132>>>(W3, b3);
    conv4_k<<<dim3(4, NIMG / 10), 120>>>(W4, b4);

    proto_k<<<BN * CCLS, 256>>>(y);
    preds_k<<<BN * TTGT, 128>>>(out);
}